// round 2
// baseline (speedup 1.0000x reference)
#include <cuda_runtime.h>
#include <cuda_bf16.h>

#define N_NODES 50000
#define N_EDGES 600000
#define LATENT 128
#define IN_FEAT 7

// ---------------- scratch (static device globals: no allocation) ----------------
__device__ float g_h[N_NODES * LATENT];
__device__ float g_x[N_NODES * LATENT];
__device__ int   g_deg_s[N_NODES];
__device__ int   g_deg_r[N_NODES];
__device__ int   g_cursor[N_NODES];
__device__ float g_inv_s[N_NODES];
__device__ float g_inv_r[N_NODES];
__device__ int   g_row_start[N_NODES + 1];
__device__ int   g_csr_sender[N_EDGES];

// ---------------- small setup kernels ----------------
__global__ void zero_kernel(int n) {
    int i = blockIdx.x * blockDim.x + threadIdx.x;
    if (i < n) { g_deg_s[i] = 0; g_deg_r[i] = 0; g_cursor[i] = 0; }
}

__global__ void degree_kernel(const int* __restrict__ senders,
                              const int* __restrict__ receivers, int e) {
    int i = blockIdx.x * blockDim.x + threadIdx.x;
    if (i < e) {
        atomicAdd(&g_deg_s[senders[i]], 1);
        atomicAdd(&g_deg_r[receivers[i]], 1);
    }
}

__global__ void invsqrt_kernel(int n) {
    int i = blockIdx.x * blockDim.x + threadIdx.x;
    if (i < n) {
        g_inv_s[i] = rsqrtf(fmaxf((float)g_deg_s[i], 1.0f));
        g_inv_r[i] = rsqrtf(fmaxf((float)g_deg_r[i], 1.0f));
    }
}

// single-block exclusive prefix scan over g_deg_r -> g_row_start
__global__ void scan_kernel(int n) {
    __shared__ int warp_sums[32];
    __shared__ int s_off;
    int tid = threadIdx.x;
    int lane = tid & 31, wid = tid >> 5;
    if (tid == 0) s_off = 0;
    __syncthreads();
    for (int base = 0; base < n; base += 1024) {
        int i = base + tid;
        int v = (i < n) ? g_deg_r[i] : 0;
        int x = v;
        #pragma unroll
        for (int d = 1; d < 32; d <<= 1) {
            int t = __shfl_up_sync(0xFFFFFFFFu, x, d);
            if (lane >= d) x += t;
        }
        if (lane == 31) warp_sums[wid] = x;
        __syncthreads();
        if (tid < 32) {
            int y = warp_sums[tid];
            #pragma unroll
            for (int d = 1; d < 32; d <<= 1) {
                int t = __shfl_up_sync(0xFFFFFFFFu, y, d);
                if (tid >= d) y += t;
            }
            warp_sums[tid] = y;
        }
        __syncthreads();
        int warp_off = (wid > 0) ? warp_sums[wid - 1] : 0;
        int excl = s_off + warp_off + x - v;
        if (i < n) g_row_start[i] = excl;
        int total = warp_sums[31];
        __syncthreads();
        if (tid == 0) s_off += total;
        __syncthreads();
    }
    if (tid == 0) g_row_start[n] = s_off;
}

__global__ void fill_kernel(const int* __restrict__ senders,
                            const int* __restrict__ receivers, int e) {
    int i = blockIdx.x * blockDim.x + threadIdx.x;
    if (i < e) {
        int r = receivers[i];
        int p = atomicAdd(&g_cursor[r], 1);
        g_csr_sender[g_row_start[r] + p] = senders[i];
    }
}

// ---------------- embed: h = nodes @ W_embed + b_embed  (warp per node) ----------------
__global__ void embed_kernel(const float* __restrict__ nodes,
                             const float* __restrict__ W_embed,
                             const float* __restrict__ b_embed, int n) {
    int warp = (blockIdx.x * blockDim.x + threadIdx.x) >> 5;
    int lane = threadIdx.x & 31;
    if (warp >= n) return;
    int node = warp;
    float nv = (lane < IN_FEAT) ? nodes[node * IN_FEAT + lane] : 0.0f;
    int f = lane * 4;
    float4 acc = *(const float4*)&b_embed[f];
    #pragma unroll
    for (int i = 0; i < IN_FEAT; i++) {
        float xi = __shfl_sync(0xFFFFFFFFu, nv, i);
        float4 w = *(const float4*)&W_embed[i * LATENT + f];
        acc.x += xi * w.x; acc.y += xi * w.y; acc.z += xi * w.z; acc.w += xi * w.w;
    }
    *(float4*)&g_h[node * LATENT + f] = acc;
}

// ---------------- fused 2-layer MLP + inv_sqrt_s scaling ----------------
// 64 nodes per block, 256 threads; thread (tn,to): 4 nodes x 8 outputs.
// NOTE: reads g_h / writes g_x via the DEVICE globals directly (passing a
// __device__ symbol as a host-side kernel argument binds the host shadow
// address — on GB300 ATS that silently reads host memory; round-1 bug).
#define MLP_SMEM ((64 * 132 + 128 * 132) * 4)
__global__ void __launch_bounds__(256, 2)
mlp_kernel(const float* __restrict__ W,     // [2,128,128] for this step
           const float* __restrict__ Bias,  // [2,128]
           int n) {
    extern __shared__ float sm[];
    float* h_s = sm;              // 64 x 132
    float* w_s = sm + 64 * 132;   // 128 x 132
    int tid = threadIdx.x;
    int nb = blockIdx.x * 64;

    // load h tile
    for (int i = tid; i < 64 * 32; i += 256) {
        int r = i >> 5, c = (i & 31) << 2;
        int node = nb + r;
        float4 v = make_float4(0.f, 0.f, 0.f, 0.f);
        if (node < n) v = *(const float4*)&g_h[node * LATENT + c];
        *(float4*)&h_s[r * 132 + c] = v;
    }

    const int to = tid & 15;   // output group: cols to*8 .. to*8+7
    const int tn = tid >> 4;   // node group:   rows tn*4 .. tn*4+3
    float acc[4][8];

    #pragma unroll
    for (int l = 0; l < 2; l++) {
        __syncthreads();  // h_s ready (l=0) / previous-layer writes visible (l=1)
        for (int i = tid; i < 128 * 32; i += 256) {
            int r = i >> 5, c = (i & 31) << 2;
            *(float4*)&w_s[r * 132 + c] = *(const float4*)&W[l * 16384 + r * LATENT + c];
        }
        __syncthreads();

        #pragma unroll
        for (int i = 0; i < 4; i++)
            #pragma unroll
            for (int j = 0; j < 8; j++)
                acc[i][j] = Bias[l * LATENT + to * 8 + j];

        #pragma unroll 2
        for (int k = 0; k < 128; k++) {
            float4 wA = *(float4*)&w_s[k * 132 + to * 8];
            float4 wB = *(float4*)&w_s[k * 132 + to * 8 + 4];
            #pragma unroll
            for (int i = 0; i < 4; i++) {
                float a = h_s[(tn * 4 + i) * 132 + k];
                acc[i][0] += a * wA.x; acc[i][1] += a * wA.y;
                acc[i][2] += a * wA.z; acc[i][3] += a * wA.w;
                acc[i][4] += a * wB.x; acc[i][5] += a * wB.y;
                acc[i][6] += a * wB.z; acc[i][7] += a * wB.w;
            }
        }

        if (l == 0) {
            // rows tn*4..+3 are read/written only by lanes of this same warp
            __syncwarp();
            #pragma unroll
            for (int i = 0; i < 4; i++)
                #pragma unroll
                for (int j = 0; j < 8; j++)
                    h_s[(tn * 4 + i) * 132 + to * 8 + j] = fmaxf(acc[i][j], 0.f);
        } else {
            #pragma unroll
            for (int i = 0; i < 4; i++) {
                int node = nb + tn * 4 + i;
                if (node < n) {
                    float sc = g_inv_s[node];
                    float4 o1 = make_float4(fmaxf(acc[i][0], 0.f) * sc, fmaxf(acc[i][1], 0.f) * sc,
                                            fmaxf(acc[i][2], 0.f) * sc, fmaxf(acc[i][3], 0.f) * sc);
                    float4 o2 = make_float4(fmaxf(acc[i][4], 0.f) * sc, fmaxf(acc[i][5], 0.f) * sc,
                                            fmaxf(acc[i][6], 0.f) * sc, fmaxf(acc[i][7], 0.f) * sc);
                    *(float4*)&g_x[node * LATENT + to * 8] = o1;
                    *(float4*)&g_x[node * LATENT + to * 8 + 4] = o2;
                }
            }
        }
    }
}

// ---------------- aggregation + skip + LayerNorm (warp per node, no atomics) ----------------
__global__ void agg_ln_kernel(const float* __restrict__ ln_scale,
                              const float* __restrict__ ln_bias, int n) {
    int warp = (blockIdx.x * blockDim.x + threadIdx.x) >> 5;
    int lane = threadIdx.x & 31;
    if (warp >= n) return;
    int node = warp;
    int rs = g_row_start[node], re = g_row_start[node + 1];
    int f = lane * 4;
    float4 acc = make_float4(0.f, 0.f, 0.f, 0.f);
    for (int i = rs; i < re; i++) {
        int s = g_csr_sender[i];
        float4 v = *(const float4*)&g_x[s * LATENT + f];
        acc.x += v.x; acc.y += v.y; acc.z += v.z; acc.w += v.w;
    }
    float ir = g_inv_r[node];
    float4 hv = *(const float4*)&g_h[node * LATENT + f];
    float4 y = make_float4(hv.x + acc.x * ir, hv.y + acc.y * ir,
                           hv.z + acc.z * ir, hv.w + acc.w * ir);
    float s1 = y.x + y.y + y.z + y.w;
    float s2 = y.x * y.x + y.y * y.y + y.z * y.z + y.w * y.w;
    #pragma unroll
    for (int off = 16; off; off >>= 1) {
        s1 += __shfl_xor_sync(0xFFFFFFFFu, s1, off);
        s2 += __shfl_xor_sync(0xFFFFFFFFu, s2, off);
    }
    float mu = s1 * (1.0f / LATENT);
    float var = s2 * (1.0f / LATENT) - mu * mu;
    float rstd = rsqrtf(var + 1e-6f);
    float4 sc = *(const float4*)&ln_scale[f];
    float4 bi = *(const float4*)&ln_bias[f];
    float4 o = make_float4((y.x - mu) * rstd * sc.x + bi.x,
                           (y.y - mu) * rstd * sc.y + bi.y,
                           (y.z - mu) * rstd * sc.z + bi.z,
                           (y.w - mu) * rstd * sc.w + bi.w);
    *(float4*)&g_h[node * LATENT + f] = o;
}

// ---------------- decode: out = h @ W_dec + b_dec (warp per node) ----------------
__global__ void decode_kernel(const float* __restrict__ W_dec,
                              const float* __restrict__ b_dec,
                              float* __restrict__ out, int n) {
    __shared__ float ws[LATENT * IN_FEAT];
    __shared__ float bs[8];
    int tid = threadIdx.x;
    for (int i = tid; i < LATENT * IN_FEAT; i += blockDim.x) ws[i] = W_dec[i];
    if (tid < IN_FEAT) bs[tid] = b_dec[tid];
    __syncthreads();
    int warp = (blockIdx.x * blockDim.x + tid) >> 5;
    int lane = tid & 31;
    if (warp >= n) return;
    int node = warp;
    int k0 = lane * 4;
    float4 hv = *(const float4*)&g_h[node * LATENT + k0];
    float p[IN_FEAT];
    #pragma unroll
    for (int j = 0; j < IN_FEAT; j++) {
        p[j] = hv.x * ws[(k0 + 0) * IN_FEAT + j] + hv.y * ws[(k0 + 1) * IN_FEAT + j]
             + hv.z * ws[(k0 + 2) * IN_FEAT + j] + hv.w * ws[(k0 + 3) * IN_FEAT + j];
    }
    #pragma unroll
    for (int off = 16; off; off >>= 1)
        #pragma unroll
        for (int j = 0; j < IN_FEAT; j++)
            p[j] += __shfl_xor_sync(0xFFFFFFFFu, p[j], off);
    if (lane == 0)
        #pragma unroll
        for (int j = 0; j < IN_FEAT; j++)
            out[node * IN_FEAT + j] = p[j] + bs[j];
}

// ---------------- launch ----------------
extern "C" void kernel_launch(void* const* d_in, const int* in_sizes, int n_in,
                              void* d_out, int out_size) {
    const float* nodes     = (const float*)d_in[0];
    const int*   senders   = (const int*)d_in[1];
    const int*   receivers = (const int*)d_in[2];
    const float* W_embed   = (const float*)d_in[3];
    const float* b_embed   = (const float*)d_in[4];
    const float* mlp_W     = (const float*)d_in[5];
    const float* mlp_b     = (const float*)d_in[6];
    const float* ln_scale  = (const float*)d_in[7];
    const float* ln_bias   = (const float*)d_in[8];
    const float* W_dec     = (const float*)d_in[9];
    const float* b_dec     = (const float*)d_in[10];
    float* out = (float*)d_out;

    int n = in_sizes[0] / IN_FEAT;   // 50000
    int e = in_sizes[1];             // 600000

    cudaFuncSetAttribute(mlp_kernel, cudaFuncAttributeMaxDynamicSharedMemorySize, MLP_SMEM);

    int nb256  = (n + 255) / 256;
    int eb256  = (e + 255) / 256;
    int warpsB = (n * 32 + 255) / 256;   // warp-per-node kernels
    int mlpB   = (n + 63) / 64;

    zero_kernel<<<nb256, 256>>>(n);
    degree_kernel<<<eb256, 256>>>(senders, receivers, e);
    invsqrt_kernel<<<nb256, 256>>>(n);
    scan_kernel<<<1, 1024>>>(n);
    fill_kernel<<<eb256, 256>>>(senders, receivers, e);
    embed_kernel<<<warpsB, 256>>>(nodes, W_embed, b_embed, n);

    for (int step = 0; step < 3; step++) {
        mlp_kernel<<<mlpB, 256, MLP_SMEM>>>(mlp_W + step * 2 * LATENT * LATENT,
                                            mlp_b + step * 2 * LATENT,
                                            n);
        agg_ln_kernel<<<warpsB, 256>>>(ln_scale + step * LATENT,
                                       ln_bias + step * LATENT, n);
    }

    decode_kernel<<<warpsB, 256>>>(W_dec, b_dec, out, n);
}

// round 4
// speedup vs baseline: 1.9629x; 1.9629x over previous
#include <cuda_runtime.h>
#include <cuda_bf16.h>

#define N_NODES 50000
#define N_EDGES 600000
#define LATENT 128
#define IN_FEAT 7

// ---------------- scratch (static device globals: no allocation) ----------------
__device__ __align__(16) float g_h[N_NODES * LATENT];
__device__ __align__(16) float g_x[N_NODES * LATENT];
__device__ int   g_deg_s[N_NODES];
__device__ int   g_deg_r[N_NODES];
__device__ int   g_cursor[N_NODES];
__device__ float g_inv_s[N_NODES];
__device__ float g_inv_r[N_NODES];
__device__ int   g_row_start[N_NODES + 1];
__device__ int   g_csr_sender[N_EDGES];
__device__ int   g_bsum[256];
__device__ int   g_boff[256];
// transposed + hi/lo split weights: [6][N=128][K=128] bf16
__device__ __align__(256) __nv_bfloat16 g_Wt_hi[6 * LATENT * LATENT];
__device__ __align__(256) __nv_bfloat16 g_Wt_lo[6 * LATENT * LATENT];

// ---------------- small setup kernels ----------------
__global__ void zero_kernel(int n) {
    int i = blockIdx.x * blockDim.x + threadIdx.x;
    if (i < n) { g_deg_s[i] = 0; g_deg_r[i] = 0; g_cursor[i] = 0; }
}

__global__ void degree_kernel(const int* __restrict__ senders,
                              const int* __restrict__ receivers, int e) {
    int i = blockIdx.x * blockDim.x + threadIdx.x;
    if (i < e) {
        atomicAdd(&g_deg_s[senders[i]], 1);
        atomicAdd(&g_deg_r[receivers[i]], 1);
    }
}

__global__ void invsqrt_kernel(int n) {
    int i = blockIdx.x * blockDim.x + threadIdx.x;
    if (i < n) {
        g_inv_s[i] = rsqrtf(fmaxf((float)g_deg_s[i], 1.0f));
        g_inv_r[i] = rsqrtf(fmaxf((float)g_deg_r[i], 1.0f));
    }
}

// ---------------- multi-block exclusive scan of g_deg_r -> g_row_start ----------------
__global__ void scan1_kernel(int n) {
    __shared__ int wsum[8];
    int t = threadIdx.x, b = blockIdx.x;
    int lane = t & 31, w = t >> 5;
    int i = b * 256 + t;
    int v = (i < n) ? g_deg_r[i] : 0;
    int x = v;
    #pragma unroll
    for (int d = 1; d < 32; d <<= 1) {
        int tmp = __shfl_up_sync(0xFFFFFFFFu, x, d);
        if (lane >= d) x += tmp;
    }
    if (lane == 31) wsum[w] = x;
    __syncthreads();
    int woff = 0;
    #pragma unroll
    for (int k = 0; k < 8; k++) if (k < w) woff += wsum[k];
    if (i < n) g_row_start[i] = woff + x - v;
    if (t == 255) g_bsum[b] = woff + x;
}

__global__ void scan2_kernel(int nb) {
    __shared__ int wsum[8];
    int t = threadIdx.x;
    int lane = t & 31, w = t >> 5;
    int v = (t < nb) ? g_bsum[t] : 0;
    int x = v;
    #pragma unroll
    for (int d = 1; d < 32; d <<= 1) {
        int tmp = __shfl_up_sync(0xFFFFFFFFu, x, d);
        if (lane >= d) x += tmp;
    }
    if (lane == 31) wsum[w] = x;
    __syncthreads();
    int woff = 0;
    #pragma unroll
    for (int k = 0; k < 8; k++) if (k < w) woff += wsum[k];
    g_boff[t] = woff + x - v;
}

__global__ void scan3_kernel(int n, int e) {
    int i = blockIdx.x * blockDim.x + threadIdx.x;
    if (i < n) g_row_start[i] += g_boff[i >> 8];
    if (i == 0) g_row_start[n] = e;
}

__global__ void fill_kernel(const int* __restrict__ senders,
                            const int* __restrict__ receivers, int e) {
    int i = blockIdx.x * blockDim.x + threadIdx.x;
    if (i < e) {
        int r = receivers[i];
        int p = atomicAdd(&g_cursor[r], 1);
        g_csr_sender[g_row_start[r] + p] = senders[i];
    }
}

// ---------------- embed ----------------
__global__ void embed_kernel(const float* __restrict__ nodes,
                             const float* __restrict__ W_embed,
                             const float* __restrict__ b_embed, int n) {
    int warp = (blockIdx.x * blockDim.x + threadIdx.x) >> 5;
    int lane = threadIdx.x & 31;
    if (warp >= n) return;
    int node = warp;
    float nv = (lane < IN_FEAT) ? nodes[node * IN_FEAT + lane] : 0.0f;
    int f = lane * 4;
    float4 acc = *(const float4*)&b_embed[f];
    #pragma unroll
    for (int i = 0; i < IN_FEAT; i++) {
        float xi = __shfl_sync(0xFFFFFFFFu, nv, i);
        float4 w = *(const float4*)&W_embed[i * LATENT + f];
        acc.x += xi * w.x; acc.y += xi * w.y; acc.z += xi * w.z; acc.w += xi * w.w;
    }
    *(float4*)&g_h[node * LATENT + f] = acc;
}

// ---------------- weight prep: transpose + bf16 hi/lo split ----------------
__global__ void prep_w_kernel(const float* __restrict__ mlp_W) {
    int i = blockIdx.x * blockDim.x + threadIdx.x;
    if (i < 6 * LATENT * LATENT) {
        int L = i >> 14;
        int r = (i >> 7) & 127;   // output (N) index
        int c = i & 127;          // input (K) index
        float w = mlp_W[(L << 14) + c * LATENT + r];   // transpose -> [N][K]
        __nv_bfloat16 hi = __float2bfloat16_rn(w);
        g_Wt_hi[i] = hi;
        g_Wt_lo[i] = __float2bfloat16_rn(w - __bfloat162float(hi));
    }
}

// ---------------- HMMA (mma.sync, baseline PTX) MLP ----------------
#define XS 136   // SMEM row stride in bf16 elems (272B -> conflict-free ldmatrix)

__device__ __forceinline__ unsigned smem_u32(const void* p) {
    unsigned a;
    asm("{ .reg .u64 t; cvta.to.shared.u64 t, %1; cvt.u32.u64 %0, t; }" : "=r"(a) : "l"(p));
    return a;
}
__device__ __forceinline__ void ldm4(unsigned* d, unsigned addr) {
    asm volatile("ldmatrix.sync.aligned.m8n8.x4.shared.b16 {%0,%1,%2,%3}, [%4];"
        : "=r"(d[0]), "=r"(d[1]), "=r"(d[2]), "=r"(d[3]) : "r"(addr));
}
__device__ __forceinline__ void mma16816(float* d, const unsigned* a, unsigned b0, unsigned b1) {
    asm volatile("mma.sync.aligned.m16n8k16.row.col.f32.bf16.bf16.f32 "
        "{%0,%1,%2,%3}, {%4,%5,%6,%7}, {%8,%9}, {%0,%1,%2,%3};"
        : "+f"(d[0]), "+f"(d[1]), "+f"(d[2]), "+f"(d[3])
        : "r"(a[0]), "r"(a[1]), "r"(a[2]), "r"(a[3]), "r"(b0), "r"(b1));
}

// one 128x128x128 layer: acc += Xhi@Whi^T + Xhi@Wlo^T + Xlo@Whi^T
__device__ __forceinline__ void compute_layer(
    unsigned bXhi, unsigned bXlo, unsigned bWhi, unsigned bWlo,
    int m0, int n0, int lane, float acc[2][8][4])
{
    int g = lane >> 3, r = lane & 7;
    int aRow = (g & 1) * 8 + r;          // ldmatrix mat order: a0,a1,a2,a3
    int aColOff = (g >> 1) * 8;
    int bRow = (g >> 1) * 8 + r;         // mats: (b0,b1) tile p*2; (b0,b1) tile p*2+1
    int bColOff = (g & 1) * 8;
    #pragma unroll
    for (int kk = 0; kk < 8; kk++) {
        int k0 = kk * 16;
        unsigned ahi[2][4], alo[2][4], bhi[4][4], blo[4][4];
        #pragma unroll
        for (int mt = 0; mt < 2; mt++) {
            unsigned off = (unsigned)(((m0 + mt * 16 + aRow) * XS + k0 + aColOff) * 2);
            ldm4(ahi[mt], bXhi + off);
            ldm4(alo[mt], bXlo + off);
        }
        #pragma unroll
        for (int p = 0; p < 4; p++) {
            unsigned off = (unsigned)(((n0 + p * 16 + bRow) * XS + k0 + bColOff) * 2);
            ldm4(bhi[p], bWhi + off);
            ldm4(blo[p], bWlo + off);
        }
        #pragma unroll
        for (int mt = 0; mt < 2; mt++)
            #pragma unroll
            for (int p = 0; p < 4; p++)
                #pragma unroll
                for (int s = 0; s < 2; s++) {
                    int nt = p * 2 + s;
                    mma16816(acc[mt][nt], ahi[mt], bhi[p][s * 2], bhi[p][s * 2 + 1]);
                    mma16816(acc[mt][nt], ahi[mt], blo[p][s * 2], blo[p][s * 2 + 1]);
                    mma16816(acc[mt][nt], alo[mt], bhi[p][s * 2], bhi[p][s * 2 + 1]);
                }
    }
}

#define MLP_SMEM (4 * 128 * XS * 2)   // Xhi, Xlo, Whi, Wlo = 139264 B

__global__ void __launch_bounds__(256, 1)
mlp_hmma_kernel(const float* __restrict__ Bias,  // [2,128] for this step
                int layer_base, int n) {
    extern __shared__ __align__(16) char smc[];
    __nv_bfloat16* Xhi = (__nv_bfloat16*)smc;
    __nv_bfloat16* Xlo = Xhi + 128 * XS;
    __nv_bfloat16* Whi = Xlo + 128 * XS;
    __nv_bfloat16* Wlo = Whi + 128 * XS;
    int tid = threadIdx.x, wid = tid >> 5, lane = tid & 31;
    int nb = blockIdx.x * 128;

    // ---- load X tile (fp32 -> hi/lo bf16) ----
    for (int t = tid; t < 2048; t += 256) {
        int row = t >> 4, col = (t & 15) << 3;
        int node = nb + row;
        float v[8] = {0.f, 0.f, 0.f, 0.f, 0.f, 0.f, 0.f, 0.f};
        if (node < n) {
            float4 a = *(const float4*)&g_h[node * LATENT + col];
            float4 b = *(const float4*)&g_h[node * LATENT + col + 4];
            v[0] = a.x; v[1] = a.y; v[2] = a.z; v[3] = a.w;
            v[4] = b.x; v[5] = b.y; v[6] = b.z; v[7] = b.w;
        }
        __align__(16) __nv_bfloat16 hi[8], lo[8];
        #pragma unroll
        for (int j = 0; j < 8; j++) {
            hi[j] = __float2bfloat16_rn(v[j]);
            lo[j] = __float2bfloat16_rn(v[j] - __bfloat162float(hi[j]));
        }
        *(uint4*)&Xhi[row * XS + col] = *(uint4*)hi;
        *(uint4*)&Xlo[row * XS + col] = *(uint4*)lo;
    }
    // ---- load W (layer 0) ----
    const __nv_bfloat16* whi = g_Wt_hi + (size_t)layer_base * LATENT * LATENT;
    const __nv_bfloat16* wlo = g_Wt_lo + (size_t)layer_base * LATENT * LATENT;
    for (int t = tid; t < 2048; t += 256) {
        int row = t >> 4, col = (t & 15) << 3;
        *(uint4*)&Whi[row * XS + col] = *(const uint4*)&whi[row * LATENT + col];
        *(uint4*)&Wlo[row * XS + col] = *(const uint4*)&wlo[row * LATENT + col];
    }
    __syncthreads();

    unsigned bXhi = smem_u32(Xhi), bXlo = smem_u32(Xlo);
    unsigned bWhi = smem_u32(Whi), bWlo = smem_u32(Wlo);
    int wm = wid >> 1, wn = wid & 1;
    int m0 = wm * 32, n0 = wn * 64;
    int tg = lane >> 2, tc = (lane & 3) * 2;

    float acc[2][8][4];
    #pragma unroll
    for (int a = 0; a < 2; a++)
        #pragma unroll
        for (int b = 0; b < 8; b++)
            #pragma unroll
            for (int c = 0; c < 4; c++) acc[a][b][c] = 0.f;

    compute_layer(bXhi, bXlo, bWhi, bWlo, m0, n0, lane, acc);
    __syncthreads();   // all layer-0 reads of X and W done

    // ---- epilogue 0: relu(D + b0) -> hi/lo back into X tiles ----
    #pragma unroll
    for (int mt = 0; mt < 2; mt++)
        #pragma unroll
        for (int h = 0; h < 2; h++) {
            int m = m0 + mt * 16 + h * 8 + tg;
            #pragma unroll
            for (int nt = 0; nt < 8; nt++) {
                int nn = n0 + nt * 8 + tc;
                float v0 = fmaxf(acc[mt][nt][h * 2 + 0] + __ldg(&Bias[nn]), 0.f);
                float v1 = fmaxf(acc[mt][nt][h * 2 + 1] + __ldg(&Bias[nn + 1]), 0.f);
                __nv_bfloat16 h0 = __float2bfloat16_rn(v0);
                __nv_bfloat16 h1 = __float2bfloat16_rn(v1);
                __nv_bfloat16 l0 = __float2bfloat16_rn(v0 - __bfloat162float(h0));
                __nv_bfloat16 l1 = __float2bfloat16_rn(v1 - __bfloat162float(h1));
                __nv_bfloat162 ph; ph.x = h0; ph.y = h1;
                __nv_bfloat162 pl; pl.x = l0; pl.y = l1;
                *(__nv_bfloat162*)&Xhi[m * XS + nn] = ph;
                *(__nv_bfloat162*)&Xlo[m * XS + nn] = pl;
            }
        }
    // ---- load W (layer 1) ----
    whi += LATENT * LATENT;
    wlo += LATENT * LATENT;
    for (int t = tid; t < 2048; t += 256) {
        int row = t >> 4, col = (t & 15) << 3;
        *(uint4*)&Whi[row * XS + col] = *(const uint4*)&whi[row * LATENT + col];
        *(uint4*)&Wlo[row * XS + col] = *(const uint4*)&wlo[row * LATENT + col];
    }
    __syncthreads();

    #pragma unroll
    for (int a = 0; a < 2; a++)
        #pragma unroll
        for (int b = 0; b < 8; b++)
            #pragma unroll
            for (int c = 0; c < 4; c++) acc[a][b][c] = 0.f;

    compute_layer(bXhi, bXlo, bWhi, bWlo, m0, n0, lane, acc);

    // ---- epilogue 1: relu(D + b1) * inv_sqrt_s -> g_x (fp32) ----
    const float* B1 = Bias + LATENT;
    #pragma unroll
    for (int mt = 0; mt < 2; mt++)
        #pragma unroll
        for (int h = 0; h < 2; h++) {
            int m = m0 + mt * 16 + h * 8 + tg;
            int node = nb + m;
            if (node < n) {
                float sc = g_inv_s[node];
                #pragma unroll
                for (int nt = 0; nt < 8; nt++) {
                    int nn = n0 + nt * 8 + tc;
                    float2 o;
                    o.x = fmaxf(acc[mt][nt][h * 2 + 0] + __ldg(&B1[nn]), 0.f) * sc;
                    o.y = fmaxf(acc[mt][nt][h * 2 + 1] + __ldg(&B1[nn + 1]), 0.f) * sc;
                    *(float2*)&g_x[node * LATENT + nn] = o;
                }
            }
        }
}

// ---------------- aggregation + skip + LayerNorm (warp per node) ----------------
__global__ void agg_ln_kernel(const float* __restrict__ ln_scale,
                              const float* __restrict__ ln_bias, int n) {
    int warp = (blockIdx.x * blockDim.x + threadIdx.x) >> 5;
    int lane = threadIdx.x & 31;
    if (warp >= n) return;
    int node = warp;
    int rs = g_row_start[node], re = g_row_start[node + 1];
    int f = lane * 4;
    float4 acc = make_float4(0.f, 0.f, 0.f, 0.f);
    for (int i = rs; i < re; i++) {
        int s = g_csr_sender[i];
        float4 v = *(const float4*)&g_x[s * LATENT + f];
        acc.x += v.x; acc.y += v.y; acc.z += v.z; acc.w += v.w;
    }
    float ir = g_inv_r[node];
    float4 hv = *(const float4*)&g_h[node * LATENT + f];
    float4 y = make_float4(hv.x + acc.x * ir, hv.y + acc.y * ir,
                           hv.z + acc.z * ir, hv.w + acc.w * ir);
    float s1 = y.x + y.y + y.z + y.w;
    float s2 = y.x * y.x + y.y * y.y + y.z * y.z + y.w * y.w;
    #pragma unroll
    for (int off = 16; off; off >>= 1) {
        s1 += __shfl_xor_sync(0xFFFFFFFFu, s1, off);
        s2 += __shfl_xor_sync(0xFFFFFFFFu, s2, off);
    }
    float mu = s1 * (1.0f / LATENT);
    float var = s2 * (1.0f / LATENT) - mu * mu;
    float rstd = rsqrtf(var + 1e-6f);
    float4 sc = *(const float4*)&ln_scale[f];
    float4 bi = *(const float4*)&ln_bias[f];
    float4 o = make_float4((y.x - mu) * rstd * sc.x + bi.x,
                           (y.y - mu) * rstd * sc.y + bi.y,
                           (y.z - mu) * rstd * sc.z + bi.z,
                           (y.w - mu) * rstd * sc.w + bi.w);
    *(float4*)&g_h[node * LATENT + f] = o;
}

// ---------------- decode ----------------
__global__ void decode_kernel(const float* __restrict__ W_dec,
                              const float* __restrict__ b_dec,
                              float* __restrict__ out, int n) {
    __shared__ float ws[LATENT * IN_FEAT];
    __shared__ float bs[8];
    int tid = threadIdx.x;
    for (int i = tid; i < LATENT * IN_FEAT; i += blockDim.x) ws[i] = W_dec[i];
    if (tid < IN_FEAT) bs[tid] = b_dec[tid];
    __syncthreads();
    int warp = (blockIdx.x * blockDim.x + tid) >> 5;
    int lane = tid & 31;
    if (warp >= n) return;
    int node = warp;
    int k0 = lane * 4;
    float4 hv = *(const float4*)&g_h[node * LATENT + k0];
    float p[IN_FEAT];
    #pragma unroll
    for (int j = 0; j < IN_FEAT; j++) {
        p[j] = hv.x * ws[(k0 + 0) * IN_FEAT + j] + hv.y * ws[(k0 + 1) * IN_FEAT + j]
             + hv.z * ws[(k0 + 2) * IN_FEAT + j] + hv.w * ws[(k0 + 3) * IN_FEAT + j];
    }
    #pragma unroll
    for (int off = 16; off; off >>= 1)
        #pragma unroll
        for (int j = 0; j < IN_FEAT; j++)
            p[j] += __shfl_xor_sync(0xFFFFFFFFu, p[j], off);
    if (lane == 0)
        #pragma unroll
        for (int j = 0; j < IN_FEAT; j++)
            out[node * IN_FEAT + j] = p[j] + bs[j];
}

// ---------------- launch ----------------
extern "C" void kernel_launch(void* const* d_in, const int* in_sizes, int n_in,
                              void* d_out, int out_size) {
    const float* nodes     = (const float*)d_in[0];
    const int*   senders   = (const int*)d_in[1];
    const int*   receivers = (const int*)d_in[2];
    const float* W_embed   = (const float*)d_in[3];
    const float* b_embed   = (const float*)d_in[4];
    const float* mlp_W     = (const float*)d_in[5];
    const float* mlp_b     = (const float*)d_in[6];
    const float* ln_scale  = (const float*)d_in[7];
    const float* ln_bias   = (const float*)d_in[8];
    const float* W_dec     = (const float*)d_in[9];
    const float* b_dec     = (const float*)d_in[10];
    float* out = (float*)d_out;

    int n = in_sizes[0] / IN_FEAT;   // 50000
    int e = in_sizes[1];             // 600000

    cudaFuncSetAttribute(mlp_hmma_kernel, cudaFuncAttributeMaxDynamicSharedMemorySize, MLP_SMEM);

    int nb256  = (n + 255) / 256;
    int eb256  = (e + 255) / 256;
    int warpsB = (n * 32 + 255) / 256;
    int mlpB   = (n + 127) / 128;
    int wprep  = (6 * LATENT * LATENT + 255) / 256;

    zero_kernel<<<nb256, 256>>>(n);
    degree_kernel<<<eb256, 256>>>(senders, receivers, e);
    invsqrt_kernel<<<nb256, 256>>>(n);
    scan1_kernel<<<nb256, 256>>>(n);
    scan2_kernel<<<1, 256>>>(nb256);
    scan3_kernel<<<nb256, 256>>>(n, e);
    fill_kernel<<<eb256, 256>>>(senders, receivers, e);
    embed_kernel<<<warpsB, 256>>>(nodes, W_embed, b_embed, n);
    prep_w_kernel<<<wprep, 256>>>(mlp_W);

    for (int step = 0; step < 3; step++) {
        mlp_hmma_kernel<<<mlpB, 256, MLP_SMEM>>>(mlp_b + step * 2 * LATENT, 2 * step, n);
        agg_ln_kernel<<<warpsB, 256>>>(ln_scale + step * LATENT,
                                       ln_bias + step * LATENT, n);
    }

    decode_kernel<<<warpsB, 256>>>(W_dec, b_dec, out, n);
}

// round 6
// speedup vs baseline: 2.2620x; 1.1524x over previous
#include <cuda_runtime.h>
#include <cuda_bf16.h>
#include <cuda_fp16.h>

#define N_NODES 50000
#define N_EDGES 600000
#define LATENT 128
#define IN_FEAT 7

// ---------------- scratch (static device globals: no allocation) ----------------
__device__ __align__(16) float  g_h[N_NODES * LATENT];
__device__ __align__(16) __half g_xh[N_NODES * LATENT];   // fp16 message payload
__device__ int   g_deg_s[N_NODES];
__device__ int   g_deg_r[N_NODES];
__device__ int   g_cursor[N_NODES];
__device__ float g_inv_s[N_NODES];
__device__ float g_inv_r[N_NODES];
__device__ int   g_row_start[N_NODES + 1];
__device__ int   g_csr_sender[N_EDGES];
__device__ int   g_bsum[256];
__device__ int   g_boff[256];
// transposed + hi/lo split weights: [6][N=128][K=128] bf16
__device__ __align__(256) __nv_bfloat16 g_Wt_hi[6 * LATENT * LATENT];
__device__ __align__(256) __nv_bfloat16 g_Wt_lo[6 * LATENT * LATENT];

// ---------------- small setup kernels ----------------
__global__ void zero_kernel(int n) {
    int i = blockIdx.x * blockDim.x + threadIdx.x;
    if (i < n) { g_deg_s[i] = 0; g_deg_r[i] = 0; g_cursor[i] = 0; }
}

__global__ void degree_kernel(const int* __restrict__ senders,
                              const int* __restrict__ receivers, int e) {
    int i = blockIdx.x * blockDim.x + threadIdx.x;
    if (i < e) {
        atomicAdd(&g_deg_s[senders[i]], 1);
        atomicAdd(&g_deg_r[receivers[i]], 1);
    }
}

// scan1 + invsqrt fused (both consume degree arrays)
__global__ void scan1_kernel(int n) {
    __shared__ int wsum[8];
    int t = threadIdx.x, b = blockIdx.x;
    int lane = t & 31, w = t >> 5;
    int i = b * 256 + t;
    int v = 0;
    if (i < n) {
        int ds = g_deg_s[i];
        v = g_deg_r[i];
        g_inv_s[i] = rsqrtf(fmaxf((float)ds, 1.0f));
        g_inv_r[i] = rsqrtf(fmaxf((float)v, 1.0f));
    }
    int x = v;
    #pragma unroll
    for (int d = 1; d < 32; d <<= 1) {
        int tmp = __shfl_up_sync(0xFFFFFFFFu, x, d);
        if (lane >= d) x += tmp;
    }
    if (lane == 31) wsum[w] = x;
    __syncthreads();
    int woff = 0;
    #pragma unroll
    for (int k = 0; k < 8; k++) if (k < w) woff += wsum[k];
    if (i < n) g_row_start[i] = woff + x - v;
    if (t == 255) g_bsum[b] = woff + x;
}

__global__ void scan2_kernel(int nb) {
    __shared__ int wsum[8];
    int t = threadIdx.x;
    int lane = t & 31, w = t >> 5;
    int v = (t < nb) ? g_bsum[t] : 0;
    int x = v;
    #pragma unroll
    for (int d = 1; d < 32; d <<= 1) {
        int tmp = __shfl_up_sync(0xFFFFFFFFu, x, d);
        if (lane >= d) x += tmp;
    }
    if (lane == 31) wsum[w] = x;
    __syncthreads();
    int woff = 0;
    #pragma unroll
    for (int k = 0; k < 8; k++) if (k < w) woff += wsum[k];
    g_boff[t] = woff + x - v;
}

__global__ void scan3_kernel(int n, int e) {
    int i = blockIdx.x * blockDim.x + threadIdx.x;
    if (i < n) g_row_start[i] += g_boff[i >> 8];
    if (i == 0) g_row_start[n] = e;
}

__global__ void fill_kernel(const int* __restrict__ senders,
                            const int* __restrict__ receivers, int e) {
    int i = blockIdx.x * blockDim.x + threadIdx.x;
    if (i < e) {
        int r = receivers[i];
        int p = atomicAdd(&g_cursor[r], 1);
        g_csr_sender[g_row_start[r] + p] = senders[i];
    }
}

// ---------------- embed ----------------
__global__ void embed_kernel(const float* __restrict__ nodes,
                             const float* __restrict__ W_embed,
                             const float* __restrict__ b_embed, int n) {
    int warp = (blockIdx.x * blockDim.x + threadIdx.x) >> 5;
    int lane = threadIdx.x & 31;
    if (warp >= n) return;
    int node = warp;
    float nv = (lane < IN_FEAT) ? nodes[node * IN_FEAT + lane] : 0.0f;
    int f = lane * 4;
    float4 acc = *(const float4*)&b_embed[f];
    #pragma unroll
    for (int i = 0; i < IN_FEAT; i++) {
        float xi = __shfl_sync(0xFFFFFFFFu, nv, i);
        float4 w = *(const float4*)&W_embed[i * LATENT + f];
        acc.x += xi * w.x; acc.y += xi * w.y; acc.z += xi * w.z; acc.w += xi * w.w;
    }
    *(float4*)&g_h[node * LATENT + f] = acc;
}

// ---------------- weight prep: transpose + bf16 hi/lo split ----------------
__global__ void prep_w_kernel(const float* __restrict__ mlp_W) {
    int i = blockIdx.x * blockDim.x + threadIdx.x;
    if (i < 6 * LATENT * LATENT) {
        int L = i >> 14;
        int r = (i >> 7) & 127;
        int c = i & 127;
        float w = mlp_W[(L << 14) + c * LATENT + r];   // transpose -> [N][K]
        __nv_bfloat16 hi = __float2bfloat16_rn(w);
        g_Wt_hi[i] = hi;
        g_Wt_lo[i] = __float2bfloat16_rn(w - __bfloat162float(hi));
    }
}

// ---------------- HMMA (mma.sync, baseline PTX) MLP ----------------
#define XS 136   // SMEM row stride in bf16 elems (272B -> conflict-free ldmatrix)
#define MROWS 64 // nodes per CTA

__device__ __forceinline__ unsigned smem_u32(const void* p) {
    unsigned a;
    asm("{ .reg .u64 t; cvta.to.shared.u64 t, %1; cvt.u32.u64 %0, t; }" : "=r"(a) : "l"(p));
    return a;
}
__device__ __forceinline__ void ldm4(unsigned* d, unsigned addr) {
    asm volatile("ldmatrix.sync.aligned.m8n8.x4.shared.b16 {%0,%1,%2,%3}, [%4];"
        : "=r"(d[0]), "=r"(d[1]), "=r"(d[2]), "=r"(d[3]) : "r"(addr));
}
__device__ __forceinline__ void mma16816(float* d, const unsigned* a, unsigned b0, unsigned b1) {
    asm volatile("mma.sync.aligned.m16n8k16.row.col.f32.bf16.bf16.f32 "
        "{%0,%1,%2,%3}, {%4,%5,%6,%7}, {%8,%9}, {%0,%1,%2,%3};"
        : "+f"(d[0]), "+f"(d[1]), "+f"(d[2]), "+f"(d[3])
        : "r"(a[0]), "r"(a[1]), "r"(a[2]), "r"(a[3]), "r"(b0), "r"(b1));
}

// one 64x128x128 layer: acc += Xhi@Whi^T + Xhi@Wlo^T + Xlo@Whi^T
// warp tile: 32(m) x 32(n); acc[mt 2][nt 4][4]
__device__ __forceinline__ void compute_layer(
    unsigned bXhi, unsigned bXlo, unsigned bWhi, unsigned bWlo,
    int m0, int n0, int lane, float acc[2][4][4])
{
    int g = lane >> 3, r = lane & 7;
    int aRow = (g & 1) * 8 + r;
    int aColOff = (g >> 1) * 8;
    int bRow = (g >> 1) * 8 + r;
    int bColOff = (g & 1) * 8;
    #pragma unroll
    for (int kk = 0; kk < 8; kk++) {
        int k0 = kk * 16;
        unsigned ahi[2][4], alo[2][4], bhi[2][4], blo[2][4];
        #pragma unroll
        for (int mt = 0; mt < 2; mt++) {
            unsigned off = (unsigned)(((m0 + mt * 16 + aRow) * XS + k0 + aColOff) * 2);
            ldm4(ahi[mt], bXhi + off);
            ldm4(alo[mt], bXlo + off);
        }
        #pragma unroll
        for (int p = 0; p < 2; p++) {
            unsigned off = (unsigned)(((n0 + p * 16 + bRow) * XS + k0 + bColOff) * 2);
            ldm4(bhi[p], bWhi + off);
            ldm4(blo[p], bWlo + off);
        }
        #pragma unroll
        for (int mt = 0; mt < 2; mt++)
            #pragma unroll
            for (int p = 0; p < 2; p++)
                #pragma unroll
                for (int s = 0; s < 2; s++) {
                    int nt = p * 2 + s;
                    mma16816(acc[mt][nt], ahi[mt], bhi[p][s * 2], bhi[p][s * 2 + 1]);
                    mma16816(acc[mt][nt], ahi[mt], blo[p][s * 2], blo[p][s * 2 + 1]);
                    mma16816(acc[mt][nt], alo[mt], bhi[p][s * 2], bhi[p][s * 2 + 1]);
                }
    }
}

#define MLP_SMEM ((2 * MROWS + 2 * 128) * XS * 2)   // 104448 B -> 2 CTAs/SM

__global__ void __launch_bounds__(256, 2)
mlp_hmma_kernel(const float* __restrict__ Bias,  // [2,128] for this step
                int layer_base, int n) {
    extern __shared__ __align__(16) char smc[];
    __nv_bfloat16* Xhi = (__nv_bfloat16*)smc;
    __nv_bfloat16* Xlo = Xhi + MROWS * XS;
    __nv_bfloat16* Whi = Xlo + MROWS * XS;
    __nv_bfloat16* Wlo = Whi + 128 * XS;
    int tid = threadIdx.x, wid = tid >> 5, lane = tid & 31;
    int nb = blockIdx.x * MROWS;

    // ---- load X tile (fp32 -> hi/lo bf16) : 64 rows x 16 threads/row ----
    for (int t = tid; t < MROWS * 16; t += 256) {
        int row = t >> 4, col = (t & 15) << 3;
        int node = nb + row;
        float v[8] = {0.f, 0.f, 0.f, 0.f, 0.f, 0.f, 0.f, 0.f};
        if (node < n) {
            float4 a = *(const float4*)&g_h[node * LATENT + col];
            float4 b = *(const float4*)&g_h[node * LATENT + col + 4];
            v[0] = a.x; v[1] = a.y; v[2] = a.z; v[3] = a.w;
            v[4] = b.x; v[5] = b.y; v[6] = b.z; v[7] = b.w;
        }
        __align__(16) __nv_bfloat16 hi[8], lo[8];
        #pragma unroll
        for (int j = 0; j < 8; j++) {
            hi[j] = __float2bfloat16_rn(v[j]);
            lo[j] = __float2bfloat16_rn(v[j] - __bfloat162float(hi[j]));
        }
        *(uint4*)&Xhi[row * XS + col] = *(uint4*)hi;
        *(uint4*)&Xlo[row * XS + col] = *(uint4*)lo;
    }
    // ---- load W (layer 0) ----
    const __nv_bfloat16* whi = g_Wt_hi + (size_t)layer_base * LATENT * LATENT;
    const __nv_bfloat16* wlo = g_Wt_lo + (size_t)layer_base * LATENT * LATENT;
    for (int t = tid; t < 2048; t += 256) {
        int row = t >> 4, col = (t & 15) << 3;
        *(uint4*)&Whi[row * XS + col] = *(const uint4*)&whi[row * LATENT + col];
        *(uint4*)&Wlo[row * XS + col] = *(const uint4*)&wlo[row * LATENT + col];
    }
    __syncthreads();

    unsigned bXhi = smem_u32(Xhi), bXlo = smem_u32(Xlo);
    unsigned bWhi = smem_u32(Whi), bWlo = smem_u32(Wlo);
    int wm = wid >> 2, wn = wid & 3;      // 2 x 4 warp grid
    int m0 = wm * 32, n0 = wn * 32;
    int tg = lane >> 2, tc = (lane & 3) * 2;

    float acc[2][4][4];
    #pragma unroll
    for (int a = 0; a < 2; a++)
        #pragma unroll
        for (int b = 0; b < 4; b++)
            #pragma unroll
            for (int c = 0; c < 4; c++) acc[a][b][c] = 0.f;

    compute_layer(bXhi, bXlo, bWhi, bWlo, m0, n0, lane, acc);
    __syncthreads();   // all layer-0 reads done

    // ---- epilogue 0: relu(D + b0) -> hi/lo back into X tiles ----
    #pragma unroll
    for (int mt = 0; mt < 2; mt++)
        #pragma unroll
        for (int h = 0; h < 2; h++) {
            int m = m0 + mt * 16 + h * 8 + tg;
            #pragma unroll
            for (int nt = 0; nt < 4; nt++) {
                int nn = n0 + nt * 8 + tc;
                float v0 = fmaxf(acc[mt][nt][h * 2 + 0] + __ldg(&Bias[nn]), 0.f);
                float v1 = fmaxf(acc[mt][nt][h * 2 + 1] + __ldg(&Bias[nn + 1]), 0.f);
                __nv_bfloat16 h0 = __float2bfloat16_rn(v0);
                __nv_bfloat16 h1 = __float2bfloat16_rn(v1);
                __nv_bfloat16 l0 = __float2bfloat16_rn(v0 - __bfloat162float(h0));
                __nv_bfloat16 l1 = __float2bfloat16_rn(v1 - __bfloat162float(h1));
                __nv_bfloat162 ph; ph.x = h0; ph.y = h1;
                __nv_bfloat162 pl; pl.x = l0; pl.y = l1;
                *(__nv_bfloat162*)&Xhi[m * XS + nn] = ph;
                *(__nv_bfloat162*)&Xlo[m * XS + nn] = pl;
            }
        }
    // ---- load W (layer 1) ----
    whi += LATENT * LATENT;
    wlo += LATENT * LATENT;
    for (int t = tid; t < 2048; t += 256) {
        int row = t >> 4, col = (t & 15) << 3;
        *(uint4*)&Whi[row * XS + col] = *(const uint4*)&whi[row * LATENT + col];
        *(uint4*)&Wlo[row * XS + col] = *(const uint4*)&wlo[row * LATENT + col];
    }
    __syncthreads();

    #pragma unroll
    for (int a = 0; a < 2; a++)
        #pragma unroll
        for (int b = 0; b < 4; b++)
            #pragma unroll
            for (int c = 0; c < 4; c++) acc[a][b][c] = 0.f;

    compute_layer(bXhi, bXlo, bWhi, bWlo, m0, n0, lane, acc);

    // ---- epilogue 1: relu(D + b1) * inv_sqrt_s -> g_xh (fp16) ----
    const float* B1 = Bias + LATENT;
    #pragma unroll
    for (int mt = 0; mt < 2; mt++)
        #pragma unroll
        for (int h = 0; h < 2; h++) {
            int m = m0 + mt * 16 + h * 8 + tg;
            int node = nb + m;
            if (node < n) {
                float sc = g_inv_s[node];
                #pragma unroll
                for (int nt = 0; nt < 4; nt++) {
                    int nn = n0 + nt * 8 + tc;
                    float2 o;
                    o.x = fmaxf(acc[mt][nt][h * 2 + 0] + __ldg(&B1[nn]), 0.f) * sc;
                    o.y = fmaxf(acc[mt][nt][h * 2 + 1] + __ldg(&B1[nn + 1]), 0.f) * sc;
                    *(__half2*)&g_xh[node * LATENT + nn] = __float22half2_rn(o);
                }
            }
        }
}

// ---------------- aggregation + skip + LayerNorm (warp per node, fp16 gather) ----------------
__global__ void agg_ln_kernel(const float* __restrict__ ln_scale,
                              const float* __restrict__ ln_bias, int n) {
    int warp = (blockIdx.x * blockDim.x + threadIdx.x) >> 5;
    int lane = threadIdx.x & 31;
    if (warp >= n) return;
    int node = warp;
    int rs = g_row_start[node], re = g_row_start[node + 1];
    int f = lane * 4;
    float4 acc = make_float4(0.f, 0.f, 0.f, 0.f);
    for (int i = rs; i < re; i++) {
        int s = g_csr_sender[i];
        uint2 raw = *(const uint2*)&g_xh[s * LATENT + f];
        float2 a = __half22float2(*(const __half2*)&raw.x);
        float2 b = __half22float2(*(const __half2*)&raw.y);
        acc.x += a.x; acc.y += a.y; acc.z += b.x; acc.w += b.y;
    }
    float ir = g_inv_r[node];
    float4 hv = *(const float4*)&g_h[node * LATENT + f];
    float4 y = make_float4(hv.x + acc.x * ir, hv.y + acc.y * ir,
                           hv.z + acc.z * ir, hv.w + acc.w * ir);
    float s1 = y.x + y.y + y.z + y.w;
    float s2 = y.x * y.x + y.y * y.y + y.z * y.z + y.w * y.w;
    #pragma unroll
    for (int off = 16; off; off >>= 1) {
        s1 += __shfl_xor_sync(0xFFFFFFFFu, s1, off);
        s2 += __shfl_xor_sync(0xFFFFFFFFu, s2, off);
    }
    float mu = s1 * (1.0f / LATENT);
    float var = s2 * (1.0f / LATENT) - mu * mu;
    float rstd = rsqrtf(var + 1e-6f);
    float4 sc = *(const float4*)&ln_scale[f];
    float4 bi = *(const float4*)&ln_bias[f];
    float4 o = make_float4((y.x - mu) * rstd * sc.x + bi.x,
                           (y.y - mu) * rstd * sc.y + bi.y,
                           (y.z - mu) * rstd * sc.z + bi.z,
                           (y.w - mu) * rstd * sc.w + bi.w);
    *(float4*)&g_h[node * LATENT + f] = o;
}

// ---------------- decode ----------------
__global__ void decode_kernel(const float* __restrict__ W_dec,
                              const float* __restrict__ b_dec,
                              float* __restrict__ out, int n) {
    __shared__ float ws[LATENT * IN_FEAT];
    __shared__ float bs[8];
    int tid = threadIdx.x;
    for (int i = tid; i < LATENT * IN_FEAT; i += blockDim.x) ws[i] = W_dec[i];
    if (tid < IN_FEAT) bs[tid] = b_dec[tid];
    __syncthreads();
    int warp = (blockIdx.x * blockDim.x + tid) >> 5;
    int lane = tid & 31;
    if (warp >= n) return;
    int node = warp;
    int k0 = lane * 4;
    float4 hv = *(const float4*)&g_h[node * LATENT + k0];
    float p[IN_FEAT];
    #pragma unroll
    for (int j = 0; j < IN_FEAT; j++) {
        p[j] = hv.x * ws[(k0 + 0) * IN_FEAT + j] + hv.y * ws[(k0 + 1) * IN_FEAT + j]
             + hv.z * ws[(k0 + 2) * IN_FEAT + j] + hv.w * ws[(k0 + 3) * IN_FEAT + j];
    }
    #pragma unroll
    for (int off = 16; off; off >>= 1)
        #pragma unroll
        for (int j = 0; j < IN_FEAT; j++)
            p[j] += __shfl_xor_sync(0xFFFFFFFFu, p[j], off);
    if (lane == 0)
        #pragma unroll
        for (int j = 0; j < IN_FEAT; j++)
            out[node * IN_FEAT + j] = p[j] + bs[j];
}

// ---------------- launch ----------------
extern "C" void kernel_launch(void* const* d_in, const int* in_sizes, int n_in,
                              void* d_out, int out_size) {
    const float* nodes     = (const float*)d_in[0];
    const int*   senders   = (const int*)d_in[1];
    const int*   receivers = (const int*)d_in[2];
    const float* W_embed   = (const float*)d_in[3];
    const float* b_embed   = (const float*)d_in[4];
    const float* mlp_W     = (const float*)d_in[5];
    const float* mlp_b     = (const float*)d_in[6];
    const float* ln_scale  = (const float*)d_in[7];
    const float* ln_bias   = (const float*)d_in[8];
    const float* W_dec     = (const float*)d_in[9];
    const float* b_dec     = (const float*)d_in[10];
    float* out = (float*)d_out;

    int n = in_sizes[0] / IN_FEAT;   // 50000
    int e = in_sizes[1];             // 600000

    cudaFuncSetAttribute(mlp_hmma_kernel, cudaFuncAttributeMaxDynamicSharedMemorySize, MLP_SMEM);

    int nb256  = (n + 255) / 256;
    int eb256  = (e + 255) / 256;
    int warpsB = (n * 32 + 255) / 256;
    int mlpB   = (n + MROWS - 1) / MROWS;
    int wprep  = (6 * LATENT * LATENT + 255) / 256;

    zero_kernel<<<nb256, 256>>>(n);
    degree_kernel<<<eb256, 256>>>(senders, receivers, e);
    scan1_kernel<<<nb256, 256>>>(n);
    scan2_kernel<<<1, 256>>>(nb256);
    scan3_kernel<<<nb256, 256>>>(n, e);
    fill_kernel<<<eb256, 256>>>(senders, receivers, e);
    embed_kernel<<<warpsB, 256>>>(nodes, W_embed, b_embed, n);
    prep_w_kernel<<<wprep, 256>>>(mlp_W);

    for (int step = 0; step < 3; step++) {
        mlp_hmma_kernel<<<mlpB, 256, MLP_SMEM>>>(mlp_b + step * 2 * LATENT, 2 * step, n);
        agg_ln_kernel<<<warpsB, 256>>>(ln_scale + step * LATENT,
                                       ln_bias + step * LATENT, n);
    }

    decode_kernel<<<warpsB, 256>>>(W_dec, b_dec, out, n);
}